// round 15
// baseline (speedup 1.0000x reference)
#include <cuda_runtime.h>
#include <cuda_bf16.h>
#include <math.h>

#define NN 20000
#define NE 320000
#define C  64
#define NG 32
#define NL 8
#define TN 64            // gemm node tile
#define TPG 313          // tiles per graph = ceil(NN/TN)
#define EBLK 1250        // edge/hist blocks per graph

#define GDC_LAUNCH() asm volatile("griddepcontrol.launch_dependents;")
#define GDC_WAIT()   asm volatile("griddepcontrol.wait;" ::: "memory")

// smem layout (floats) for k_gemm — fp32 weights, split-on-the-fly
#define WS_STR 132
#define HS_STR 68
#define SM_WS  0                       // 64*132 fp32 weights [k][c(0..127)]
#define SM_HSH (SM_WS + 64*WS_STR)     // 8448
#define SM_HSL (SM_HSH + 64*HS_STR)    // 12800
#define SM_BC  (SM_HSL + 64*HS_STR)    // 17152
#define SM_MUS (SM_BC + 128)           // 17280
#define SM_RSS (SM_MUS + 64)           // 17344
#define SM_TOT (SM_RSS + 64)           // 17408 floats = 69632 B

__device__ __forceinline__ unsigned f2tf(float x){
    unsigned r; asm("cvt.rna.tf32.f32 %0, %1;" : "=r"(r) : "f"(x)); return r;
}
#define MMA_TF32(c, a0,a1,a2,a3, b0,b1) \
    asm volatile("mma.sync.aligned.m16n8k8.row.col.f32.tf32.tf32.f32 " \
        "{%0,%1,%2,%3},{%4,%5,%6,%7},{%8,%9},{%0,%1,%2,%3};" \
        : "+f"(c[0]),"+f"(c[1]),"+f"(c[2]),"+f"(c[3]) \
        : "r"(a0),"r"(a1),"r"(a2),"r"(a3),"r"(b0),"r"(b1))

// ---------------- scratch: [2] = per-graph --------------------------------
__device__ unsigned g_xlb[2][NN*32];   // xl in bf16x2 (32 words = 64 feats/node)
__device__ float4 g_xr4[2][NN*16];
__device__ float4 g_g4 [2][NN*16];
__device__ float  g_h  [2][NN*C];
__device__ int    g_rowptr[2][NN+1];
__device__ int    g_cursor[2][NN];
__device__ int    g_col[2][NE];
__device__ int    g_blks[2][32];
__device__ float  g_bnsum[2][2][C];
__device__ float  g_bnsq [2][2][C];
__device__ float  g_pool[2*NG*C];
__device__ float  g_pcnt[2*NG];

// ---------------- per-graph CSR build (normal launches) ---------------------
__global__ void __launch_bounds__(1024) k_zero(int gr){
    int i = blockIdx.x*1024 + threadIdx.x;
    if (i < NN) g_cursor[gr][i] = 0;
    if (i < NG*C) g_pool[gr*NG*C + i] = 0.f;
    if (i < NG)   g_pcnt[gr*NG + i] = 0.f;
}
__global__ void k_hist(const int* __restrict__ ei, int gr){
    int e = blockIdx.x*256 + threadIdx.x;
    if (e < NE) atomicAdd(&g_cursor[gr][ei[NE + e]], 1);
}
__global__ void __launch_bounds__(1024) k_scan1(int gr){
    __shared__ int s[1024];
    int blk = blockIdx.x;
    int tid = threadIdx.x;
    int gid = blk*1024 + tid;
    int v = (gid < NN) ? g_cursor[gr][gid] : 0;
    s[tid] = v; __syncthreads();
    for (int off=1; off<1024; off<<=1){
        int t = (tid>=off) ? s[tid-off] : 0;
        __syncthreads();
        s[tid] += t;
        __syncthreads();
    }
    if (gid < NN) g_rowptr[gr][gid] = s[tid] - v;
    if (tid == 1023) g_blks[gr][blk] = s[1023];
}
__global__ void __launch_bounds__(1024) k_scan3(int gr){
    __shared__ int sadd;
    int blk = blockIdx.x;
    if (threadIdx.x == 0){
        int r = 0;
        for (int i=0;i<blk;i++) r += g_blks[gr][i];
        sadd = r;
        if (blk == 19) g_rowptr[gr][NN] = r + g_blks[gr][19];
    }
    __syncthreads();
    int add = sadd;
    int gid = blk*1024 + threadIdx.x;
    if (gid < NN){
        int v = g_rowptr[gr][gid] + add;
        g_rowptr[gr][gid] = v;
        g_cursor[gr][gid] = v;
    }
}
__global__ void k_scatter(const int* __restrict__ ei, int gr){
    int e = blockIdx.x*256 + threadIdx.x;
    if (e < NE){
        int d = ei[NE+e], s = ei[e];
        int p = atomicAdd(&g_cursor[gr][d], 1);
        g_col[gr][p] = s;
    }
}

// ---------------- fused update + dual GEMM: 3xTF32, 3 blocks/SM -------------
__global__ void __launch_bounds__(256,3) k_gemm(
        const float* __restrict__ Wl, const float* __restrict__ bl,
        const float* __restrict__ Wr, const float* __restrict__ br,
        const float* __restrict__ gamma, const float* __restrict__ beta,
        int layer, int gr,
        const float* __restrict__ x,
        const float* __restrict__ Wn, const float* __restrict__ bnode)
{
    extern __shared__ float sm[];
    float* ws  = sm + SM_WS;
    float* hsh = sm + SM_HSH;
    float* hsl = sm + SM_HSL;
    float* bc  = sm + SM_BC;
    float* mus = sm + SM_MUS;
    float* rss = sm + SM_RSS;
    __shared__ float wn[320];
    __shared__ float xs[TN*5];

    GDC_LAUNCH();

    int tid  = threadIdx.x;
    int n0t  = blockIdx.x * TN;
    const float* g_hf = g_h[gr];
    const float* g_gf = (const float*)g_g4[gr];

    // ---- safe prologue (inputs only): weights fp32 into smem ----
    for (int i=tid;i<64*128;i+=256){
        int k=i>>7, c=i&127;
        ws[k*WS_STR+c] = (c<64) ? Wl[k*64+c] : Wr[k*64+(c-64)];
    }
    if (tid < 128) bc[tid] = (tid<64) ? bl[tid] : br[tid-64];
    if (layer == 0){
        for (int i=tid;i<320;i+=256) wn[i] = Wn[i];
        for (int i=tid;i<TN*5;i+=256){
            int gi = n0t*5 + i;
            xs[i] = (gi < NN*5) ? x[gi] : 0.f;
        }
    }

    GDC_WAIT();

    if (blockIdx.x == 0 && tid >= 128 && tid < 256){
        int nb = layer & 1, t = tid - 128;
        if (t < 64) g_bnsum[gr][nb][t] = 0.f; else g_bnsq[gr][nb][t-64] = 0.f;
    }

    if (layer == 0){
        __syncthreads();
        for (int i=tid;i<TN*64;i+=256){
            int nl=i>>6, c=i&63; int n=n0t+nl;
            float a = bnode[c];
            #pragma unroll
            for (int k=0;k<5;k++) a = fmaf(xs[nl*5+k], wn[k*64+c], a);
            if (n < NN) g_h[gr][n*64+c] = a; else a = 0.f;
            unsigned hb = f2tf(a);
            float hi = __uint_as_float(hb);
            hsh[nl*HS_STR+c] = hi;
            hsl[nl*HS_STR+c] = __uint_as_float(f2tf(a - hi));
        }
    } else {
        int pb = (layer-1)&1;
        if (tid < 64){
            float mu = g_bnsum[gr][pb][tid]*(1.f/NN);
            float va = g_bnsq[gr][pb][tid]*(1.f/NN) - mu*mu;
            mus[tid] = mu;
            rss[tid] = rsqrtf(va + 1e-5f) * gamma[tid];
        }
        __syncthreads();
        for (int i=tid;i<TN*64;i+=256){
            int nl=i>>6, c=i&63; int n=n0t+nl;
            float hv = 0.f;
            if (n < NN){
                float g  = g_gf[n*64+c];
                float gh = (g - mus[c])*rss[c] + beta[c];
                float el = (gh > 0.f) ? gh : (__expf(gh)-1.f);
                hv = g_hf[n*64+c] + el;
                g_h[gr][n*64+c] = hv;
            }
            unsigned hb = f2tf(hv);
            float hi = __uint_as_float(hb);
            hsh[nl*HS_STR+c] = hi;
            hsl[nl*HS_STR+c] = __uint_as_float(f2tf(hv - hi));
        }
    }
    __syncthreads();

    // ---- tensor-core mainloop: warp tile m32 x n32, 3xTF32 ----
    int lane = tid & 31, wid = tid >> 5;
    int g   = lane >> 2, tig = lane & 3;
    int mgrp = wid & 1;
    int ngrp = wid >> 1;

    float acc[2][4][4];
    #pragma unroll
    for (int nf=0;nf<4;nf++){
        float c0 = bc[ngrp*32 + nf*8 + 2*tig];
        float c1 = bc[ngrp*32 + nf*8 + 2*tig + 1];
        #pragma unroll
        for (int mt=0;mt<2;mt++){
            acc[mt][nf][0]=c0; acc[mt][nf][1]=c1;
            acc[mt][nf][2]=c0; acc[mt][nf][3]=c1;
        }
    }

    #pragma unroll
    for (int kc=0;kc<64;kc+=8){
        unsigned ah[2][4], al[2][4];
        #pragma unroll
        for (int mt=0;mt<2;mt++){
            int m = mgrp*32 + mt*16 + g;
            ah[mt][0] = __float_as_uint(hsh[m*HS_STR     + kc+tig]);
            ah[mt][1] = __float_as_uint(hsh[(m+8)*HS_STR + kc+tig]);
            ah[mt][2] = __float_as_uint(hsh[m*HS_STR     + kc+tig+4]);
            ah[mt][3] = __float_as_uint(hsh[(m+8)*HS_STR + kc+tig+4]);
            al[mt][0] = __float_as_uint(hsl[m*HS_STR     + kc+tig]);
            al[mt][1] = __float_as_uint(hsl[(m+8)*HS_STR + kc+tig]);
            al[mt][2] = __float_as_uint(hsl[m*HS_STR     + kc+tig+4]);
            al[mt][3] = __float_as_uint(hsl[(m+8)*HS_STR + kc+tig+4]);
        }
        #pragma unroll
        for (int nf=0;nf<4;nf++){
            int n = ngrp*32 + nf*8 + g;
            float w0 = ws[(kc+tig)*WS_STR   + n];
            float w1 = ws[(kc+tig+4)*WS_STR + n];
            unsigned bh0 = f2tf(w0);
            unsigned bh1 = f2tf(w1);
            unsigned bl0 = f2tf(w0 - __uint_as_float(bh0));
            unsigned bl1 = f2tf(w1 - __uint_as_float(bh1));
            #pragma unroll
            for (int mt=0;mt<2;mt++){
                MMA_TF32(acc[mt][nf], ah[mt][0],ah[mt][1],ah[mt][2],ah[mt][3], bh0,bh1);
                MMA_TF32(acc[mt][nf], ah[mt][0],ah[mt][1],ah[mt][2],ah[mt][3], bl0,bl1);
                MMA_TF32(acc[mt][nf], al[mt][0],al[mt][1],al[mt][2],al[mt][3], bh0,bh1);
            }
        }
    }

    // ---- epilogue: xl -> bf16x2 (g_xlb), xr -> fp32 (g_xr4) ----
    unsigned* xlb = g_xlb[gr];
    float2* xr2 = (float2*)g_xr4[gr];
    #pragma unroll
    for (int mt=0;mt<2;mt++){
        int r0 = n0t + mgrp*32 + mt*16 + g;
        #pragma unroll
        for (int nf=0;nf<4;nf++){
            int cg = ngrp*32 + nf*8 + 2*tig;
            if (cg < 64){
                __nv_bfloat162 v0 = __floats2bfloat162_rn(acc[mt][nf][0], acc[mt][nf][1]);
                __nv_bfloat162 v1 = __floats2bfloat162_rn(acc[mt][nf][2], acc[mt][nf][3]);
                if (r0 < NN)   xlb[r0*32 + (cg>>1)]     = *(unsigned*)&v0;
                if (r0+8 < NN) xlb[(r0+8)*32 + (cg>>1)] = *(unsigned*)&v1;
            } else {
                int cc = cg - 64;
                float2 v0 = make_float2(acc[mt][nf][0], acc[mt][nf][1]);
                float2 v1 = make_float2(acc[mt][nf][2], acc[mt][nf][3]);
                if (r0 < NN)   xr2[r0*32 + (cc>>1)]     = v0;
                if (r0+8 < NN) xr2[(r0+8)*32 + (cc>>1)] = v1;
            }
        }
    }
}

// unpack uint2 (2x bf16x2) -> float4
__device__ __forceinline__ float4 bf2f4(uint2 u){
    __nv_bfloat162 b0 = *reinterpret_cast<__nv_bfloat162*>(&u.x);
    __nv_bfloat162 b1 = *reinterpret_cast<__nv_bfloat162*>(&u.y);
    float2 f0 = __bfloat1622float2(b0);
    float2 f1 = __bfloat1622float2(b1);
    return make_float4(f0.x, f0.y, f1.x, f1.y);
}

// ---------------- edge aggregation: bf16 xl gather, self-ref softmax --------
__global__ void __launch_bounds__(256) k_edge(const float* __restrict__ att,
                                              const float* __restrict__ cb,
                                              int layer, int gr)
{
    __shared__ float bsum[C], bsq[C];

    GDC_LAUNCH();

    int tid = threadIdx.x;
    int n   = blockIdx.x*16 + (tid>>4);
    int l16 = tid & 15;
    unsigned gmask = 0xFu << ((tid&31) & ~3);
    const uint2* xlb = (const uint2*)g_xlb[gr];

    if (tid < C){ bsum[tid]=0.f; bsq[tid]=0.f; }
    float4 a  = ((const float4*)att)[l16];
    float4 cb4= ((const float4*)cb)[l16];
    __syncthreads();

    GDC_WAIT();

    float4 xr = g_xr4[gr][n*16 + l16];
    float4 xls = bf2f4(xlb[n*16 + l16]);
    float pself;
    {
        float e0 = xls.x + xr.x; e0 = (e0>0.f)? e0 : 0.2f*e0;
        float e1 = xls.y + xr.y; e1 = (e1>0.f)? e1 : 0.2f*e1;
        float e2 = xls.z + xr.z; e2 = (e2>0.f)? e2 : 0.2f*e2;
        float e3 = xls.w + xr.w; e3 = (e3>0.f)? e3 : 0.2f*e3;
        float p = fmaf(e0,a.x, fmaf(e1,a.y, fmaf(e2,a.z, e3*a.w)));
        p += __shfl_xor_sync(gmask, p, 1, 4);
        p += __shfl_xor_sync(gmask, p, 2, 4);
        pself = p;
    }

    float sA = 1.f, sB = 0.f;
    float4 oA = xls;
    float4 oB = make_float4(0.f,0.f,0.f,0.f);
    int beg = g_rowptr[gr][n], end = g_rowptr[gr][n+1];
    const int* col = g_col[gr];
    int j = beg;
    for (; j+1 < end; j += 2){
        int srcA = col[j], srcB = col[j+1];
        float4 xA = bf2f4(xlb[srcA*16 + l16]);
        float4 xB = bf2f4(xlb[srcB*16 + l16]);
        float a0 = xA.x + xr.x; a0 = (a0>0.f)? a0 : 0.2f*a0;
        float a1 = xA.y + xr.y; a1 = (a1>0.f)? a1 : 0.2f*a1;
        float a2 = xA.z + xr.z; a2 = (a2>0.f)? a2 : 0.2f*a2;
        float a3 = xA.w + xr.w; a3 = (a3>0.f)? a3 : 0.2f*a3;
        float b0 = xB.x + xr.x; b0 = (b0>0.f)? b0 : 0.2f*b0;
        float b1 = xB.y + xr.y; b1 = (b1>0.f)? b1 : 0.2f*b1;
        float b2 = xB.z + xr.z; b2 = (b2>0.f)? b2 : 0.2f*b2;
        float b3 = xB.w + xr.w; b3 = (b3>0.f)? b3 : 0.2f*b3;
        float pA = fmaf(a0,a.x, fmaf(a1,a.y, fmaf(a2,a.z, a3*a.w)));
        float pB = fmaf(b0,a.x, fmaf(b1,a.y, fmaf(b2,a.z, b3*a.w)));
        pA += __shfl_xor_sync(gmask, pA, 1, 4);
        pB += __shfl_xor_sync(gmask, pB, 1, 4);
        pA += __shfl_xor_sync(gmask, pA, 2, 4);
        pB += __shfl_xor_sync(gmask, pB, 2, 4);
        float wA = __expf(pA - pself);
        float wB = __expf(pB - pself);
        sA += wA; sB += wB;
        oA.x = fmaf(wA, xA.x, oA.x);
        oA.y = fmaf(wA, xA.y, oA.y);
        oA.z = fmaf(wA, xA.z, oA.z);
        oA.w = fmaf(wA, xA.w, oA.w);
        oB.x = fmaf(wB, xB.x, oB.x);
        oB.y = fmaf(wB, xB.y, oB.y);
        oB.z = fmaf(wB, xB.z, oB.z);
        oB.w = fmaf(wB, xB.w, oB.w);
    }
    if (j < end){
        int src = col[j];
        float4 xl = bf2f4(xlb[src*16 + l16]);
        float e0 = xl.x + xr.x; e0 = (e0>0.f)? e0 : 0.2f*e0;
        float e1 = xl.y + xr.y; e1 = (e1>0.f)? e1 : 0.2f*e1;
        float e2 = xl.z + xr.z; e2 = (e2>0.f)? e2 : 0.2f*e2;
        float e3 = xl.w + xr.w; e3 = (e3>0.f)? e3 : 0.2f*e3;
        float p = fmaf(e0,a.x, fmaf(e1,a.y, fmaf(e2,a.z, e3*a.w)));
        p += __shfl_xor_sync(gmask, p, 1, 4);
        p += __shfl_xor_sync(gmask, p, 2, 4);
        float w = __expf(p - pself);
        sA += w;
        oA.x = fmaf(w, xl.x, oA.x);
        oA.y = fmaf(w, xl.y, oA.y);
        oA.z = fmaf(w, xl.z, oA.z);
        oA.w = fmaf(w, xl.w, oA.w);
    }
    float s = sA + sB;
    float4 o = make_float4(oA.x+oB.x, oA.y+oB.y, oA.z+oB.z, oA.w+oB.w);
    float inv = 1.f/s;
    float4 gv = make_float4(fmaf(o.x,inv,cb4.x), fmaf(o.y,inv,cb4.y),
                            fmaf(o.z,inv,cb4.z), fmaf(o.w,inv,cb4.w));
    g_g4[gr][n*16 + l16] = gv;

    float q0=gv.x, q1=gv.y, q2=gv.z, q3=gv.w;
    float r0=q0*q0, r1=q1*q1, r2=q2*q2, r3=q3*q3;
    q0 += __shfl_xor_sync(0xffffffffu, q0, 16);
    q1 += __shfl_xor_sync(0xffffffffu, q1, 16);
    q2 += __shfl_xor_sync(0xffffffffu, q2, 16);
    q3 += __shfl_xor_sync(0xffffffffu, q3, 16);
    r0 += __shfl_xor_sync(0xffffffffu, r0, 16);
    r1 += __shfl_xor_sync(0xffffffffu, r1, 16);
    r2 += __shfl_xor_sync(0xffffffffu, r2, 16);
    r3 += __shfl_xor_sync(0xffffffffu, r3, 16);
    if ((tid & 31) < 16){
        atomicAdd(&bsum[l16*4+0], q0); atomicAdd(&bsum[l16*4+1], q1);
        atomicAdd(&bsum[l16*4+2], q2); atomicAdd(&bsum[l16*4+3], q3);
        atomicAdd(&bsq [l16*4+0], r0); atomicAdd(&bsq [l16*4+1], r1);
        atomicAdd(&bsq [l16*4+2], r2); atomicAdd(&bsq [l16*4+3], r3);
    }
    __syncthreads();
    if (tid < C){
        int b = layer & 1;
        atomicAdd(&g_bnsum[gr][b][tid], bsum[tid]);
        atomicAdd(&g_bnsq [gr][b][tid], bsq[tid]);
    }
}

// ---------------- pool with fused final update (both graphs, PDL) -----------
__global__ void __launch_bounds__(256) k_pool(const int* __restrict__ b0,
                                              const int* __restrict__ b1,
                                              const float* __restrict__ gamma,
                                              const float* __restrict__ beta)
{
    __shared__ float mus[C], rss[C];
    GDC_LAUNCH();
    GDC_WAIT();
    int gr = blockIdx.x >= 100;
    int blk = blockIdx.x - gr*100;
    const int* batch = gr ? b1 : b0;
    int tid = threadIdx.x;
    if (tid < C){
        float mu = g_bnsum[gr][1][tid]*(1.f/NN);
        float va = g_bnsq[gr][1][tid]*(1.f/NN) - mu*mu;
        mus[tid] = mu;
        rss[tid] = rsqrtf(va + 1e-5f) * gamma[tid];
    }
    __syncthreads();
    const float* g_gf = (const float*)g_g4[gr];
    const float* g_hf = g_h[gr];
    int c = tid & 63, ng = tid >> 6;
    int n0 = blk * 200;
    float acc = 0.f, cnt = 0.f;
    int cur = -1;
    for (int i=ng; i<200; i+=4){
        int n = n0 + i;
        if (n >= NN) break;
        float g  = g_gf[n*64+c];
        float gh = (g - mus[c])*rss[c] + beta[c];
        float el = (gh > 0.f) ? gh : (__expf(gh)-1.f);
        float hv = g_hf[n*64+c] + el;
        int b = batch[n];
        if (b != cur){
            if (cur >= 0){
                atomicAdd(&g_pool[gr*NG*C + cur*C + c], acc);
                if (c == 0) atomicAdd(&g_pcnt[gr*NG + cur], cnt);
            }
            cur = b; acc = 0.f; cnt = 0.f;
        }
        acc += hv; cnt += 1.f;
    }
    if (cur >= 0){
        atomicAdd(&g_pool[gr*NG*C + cur*C + c], acc);
        if (c == 0) atomicAdd(&g_pcnt[gr*NG + cur], cnt);
    }
}

// ---------------- head MLP (normal launch) ----------------------------------
__global__ void __launch_bounds__(256) k_head(
        const float* __restrict__ f1w, const float* __restrict__ f1b,
        const float* __restrict__ f2w, const float* __restrict__ f2b,
        const float* __restrict__ f3w, const float* __restrict__ f3b,
        float* __restrict__ out)
{
    __shared__ float cvec[128], h1[256], h2[128];
    int b = blockIdx.x, tid = threadIdx.x;
    if (tid < 64)
        cvec[tid] = g_pool[b*C+tid] / fmaxf(g_pcnt[b], 1.f);
    else if (tid < 128)
        cvec[tid] = g_pool[NG*C + b*C + (tid-64)] / fmaxf(g_pcnt[NG+b], 1.f);
    __syncthreads();
    float a = f1b[tid];
    for (int k=0;k<128;k++) a = fmaf(cvec[k], f1w[k*256+tid], a);
    h1[tid] = fmaxf(a, 0.f);
    __syncthreads();
    if (tid < 128){
        float a2 = f2b[tid];
        for (int k=0;k<256;k++) a2 = fmaf(h1[k], f2w[k*128+tid], a2);
        h2[tid] = fmaxf(a2, 0.f);
    }
    __syncthreads();
    if (tid == 0){
        float a3 = f3b[0];
        for (int k=0;k<128;k++) a3 = fmaf(h2[k], f3w[k], a3);
        out[b] = a3;
    }
}

// ---------------- launch ----------------------------------------------------
extern "C" void kernel_launch(void* const* d_in, const int* in_sizes, int n_in,
                              void* d_out, int out_size){
    const float *x[2]; const int *ei[2]; const int *bt[2];
    if (in_sizes[1] == 2*NE){
        x[0]=(const float*)d_in[0]; ei[0]=(const int*)d_in[1]; bt[0]=(const int*)d_in[2];
        x[1]=(const float*)d_in[3]; ei[1]=(const int*)d_in[4]; bt[1]=(const int*)d_in[5];
    } else {
        x[0]=(const float*)d_in[0]; x[1]=(const float*)d_in[1];
        ei[0]=(const int*)d_in[2]; ei[1]=(const int*)d_in[3];
        bt[0]=(const int*)d_in[4]; bt[1]=(const int*)d_in[5];
    }
    const float* Wn    =(const float*)d_in[6];
    const float* bnode =(const float*)d_in[7];
    const float* Wl    =(const float*)d_in[8];
    const float* bl    =(const float*)d_in[9];
    const float* Wr    =(const float*)d_in[10];
    const float* br    =(const float*)d_in[11];
    const float* att   =(const float*)d_in[12];
    const float* cbias =(const float*)d_in[13];
    const float* gamma =(const float*)d_in[14];
    const float* beta  =(const float*)d_in[15];
    const float* f1w   =(const float*)d_in[16];
    const float* f1b   =(const float*)d_in[17];
    const float* f2w   =(const float*)d_in[18];
    const float* f2b   =(const float*)d_in[19];
    const float* f3w   =(const float*)d_in[20];
    const float* f3b   =(const float*)d_in[21];

    int gsm = SM_TOT * 4;
    cudaFuncSetAttribute(k_gemm, cudaFuncAttributeMaxDynamicSharedMemorySize, gsm);

    static cudaStream_t s2 = 0;
    static cudaEvent_t  efk = 0, ejn = 0;
    if (!s2){
        cudaStreamCreateWithFlags(&s2, cudaStreamNonBlocking);
        cudaEventCreateWithFlags(&efk, cudaEventDisableTiming);
        cudaEventCreateWithFlags(&ejn, cudaEventDisableTiming);
    }
    cudaStream_t s0 = 0;

    cudaEventRecord(efk, s0);
    cudaStreamWaitEvent(s2, efk, 0);

    cudaLaunchAttribute pdl[1];
    pdl[0].id = cudaLaunchAttributeProgrammaticStreamSerialization;
    pdl[0].val.programmaticStreamSerializationAllowed = 1;

    for (int g=0; g<2; g++){
        cudaStream_t st = g ? s2 : s0;
        k_zero   <<<(NN+1023)/1024,1024,0,st>>>(g);
        k_hist   <<<EBLK,256,0,st>>>(ei[g], g);
        k_scan1  <<<20,1024,0,st>>>(g);
        k_scan3  <<<20,1024,0,st>>>(g);
        k_scatter<<<EBLK,256,0,st>>>(ei[g], g);
        for (int l=0;l<NL;l++){
            {
                cudaLaunchConfig_t cfg = {};
                cfg.gridDim = dim3(TPG,1,1); cfg.blockDim = dim3(256,1,1);
                cfg.dynamicSmemBytes = gsm; cfg.stream = st;
                cfg.attrs = pdl; cfg.numAttrs = 1;
                cudaLaunchKernelEx(&cfg, k_gemm,
                    Wl+l*C*C, bl+l*C, Wr+l*C*C, br+l*C,
                    gamma+l*C, beta+l*C, l, g, x[g], Wn, bnode);
            }
            {
                cudaLaunchConfig_t cfg = {};
                cfg.gridDim = dim3(EBLK,1,1); cfg.blockDim = dim3(256,1,1);
                cfg.dynamicSmemBytes = 0; cfg.stream = st;
                cfg.attrs = pdl; cfg.numAttrs = 1;
                cudaLaunchKernelEx(&cfg, k_edge,
                    att+l*C, cbias+l*C, l, g);
            }
        }
    }

    cudaEventRecord(ejn, s2);
    cudaStreamWaitEvent(s0, ejn, 0);

    {
        cudaLaunchConfig_t cfg = {};
        cfg.gridDim = dim3(200,1,1); cfg.blockDim = dim3(256,1,1);
        cfg.dynamicSmemBytes = 0; cfg.stream = s0;
        cfg.attrs = pdl; cfg.numAttrs = 1;
        cudaLaunchKernelEx(&cfg, k_pool, bt[0], bt[1], gamma+7*C, beta+7*C);
    }
    k_head<<<NG,256,0,s0>>>(f1w,f1b,f2w,f2b,f3w,f3b,(float*)d_out);
}

// round 16
// speedup vs baseline: 1.0137x; 1.0137x over previous
#include <cuda_runtime.h>
#include <math.h>

#define NN 20000
#define NE 320000
#define C  64
#define NG 32
#define NL 8
#define TN 64            // gemm node tile
#define TPG 313          // tiles per graph = ceil(NN/TN)
#define EBLK 1250        // edge/hist blocks per graph

#define GDC_LAUNCH() asm volatile("griddepcontrol.launch_dependents;")
#define GDC_WAIT()   asm volatile("griddepcontrol.wait;" ::: "memory")

// smem layout (floats) for k_gemm — fp32 weights, split-on-the-fly
#define WS_STR 132
#define HS_STR 68
#define SM_WS  0                       // 64*132 fp32 weights [k][c(0..127)]
#define SM_HSH (SM_WS + 64*WS_STR)     // 8448
#define SM_HSL (SM_HSH + 64*HS_STR)    // 12800
#define SM_BC  (SM_HSL + 64*HS_STR)    // 17152
#define SM_MUS (SM_BC + 128)           // 17280
#define SM_RSS (SM_MUS + 64)           // 17344
#define SM_TOT (SM_RSS + 64)           // 17408 floats = 69632 B

__device__ __forceinline__ unsigned f2tf(float x){
    unsigned r; asm("cvt.rna.tf32.f32 %0, %1;" : "=r"(r) : "f"(x)); return r;
}
#define MMA_TF32(c, a0,a1,a2,a3, b0,b1) \
    asm volatile("mma.sync.aligned.m16n8k8.row.col.f32.tf32.tf32.f32 " \
        "{%0,%1,%2,%3},{%4,%5,%6,%7},{%8,%9},{%0,%1,%2,%3};" \
        : "+f"(c[0]),"+f"(c[1]),"+f"(c[2]),"+f"(c[3]) \
        : "r"(a0),"r"(a1),"r"(a2),"r"(a3),"r"(b0),"r"(b1))

// ---------------- scratch: [2] = per-graph --------------------------------
__device__ float4 g_xl4[2][NN*16];
__device__ float4 g_xr4[2][NN*16];
__device__ float4 g_g4 [2][NN*16];
__device__ float  g_h  [2][NN*C];
__device__ int    g_rowptr[2][NN+1];
__device__ int    g_cursor[2][NN];
__device__ int    g_col[2][NE];
__device__ int    g_blks[2][32];
__device__ float  g_bnsum[2][2][C];
__device__ float  g_bnsq [2][2][C];
__device__ float  g_pool[2*NG*C];
__device__ float  g_pcnt[2*NG];

// ---------------- per-graph CSR build (PDL chain) ----------------------------
__global__ void __launch_bounds__(1024) k_zero(int gr){
    int i = blockIdx.x*1024 + threadIdx.x;
    if (i < NN) g_cursor[gr][i] = 0;
    if (i < NG*C) g_pool[gr*NG*C + i] = 0.f;
    if (i < NG)   g_pcnt[gr*NG + i] = 0.f;
    GDC_LAUNCH();
}
__global__ void k_hist(const int* __restrict__ ei, int gr){
    GDC_LAUNCH();
    int e = blockIdx.x*256 + threadIdx.x;
    int d = (e < NE) ? ei[NE + e] : 0;       // input prefetch (safe pre-wait)
    GDC_WAIT();
    if (e < NE) atomicAdd(&g_cursor[gr][d], 1);
}
__global__ void __launch_bounds__(1024) k_scan1(int gr){
    __shared__ int s[1024];
    GDC_LAUNCH();
    GDC_WAIT();
    int blk = blockIdx.x;
    int tid = threadIdx.x;
    int gid = blk*1024 + tid;
    int v = (gid < NN) ? g_cursor[gr][gid] : 0;
    s[tid] = v; __syncthreads();
    for (int off=1; off<1024; off<<=1){
        int t = (tid>=off) ? s[tid-off] : 0;
        __syncthreads();
        s[tid] += t;
        __syncthreads();
    }
    if (gid < NN) g_rowptr[gr][gid] = s[tid] - v;
    if (tid == 1023) g_blks[gr][blk] = s[1023];
}
__global__ void __launch_bounds__(1024) k_scan3(int gr){
    __shared__ int sadd;
    GDC_LAUNCH();
    GDC_WAIT();
    int blk = blockIdx.x;
    if (threadIdx.x == 0){
        int r = 0;
        for (int i=0;i<blk;i++) r += g_blks[gr][i];
        sadd = r;
        if (blk == 19) g_rowptr[gr][NN] = r + g_blks[gr][19];
    }
    __syncthreads();
    int add = sadd;
    int gid = blk*1024 + threadIdx.x;
    if (gid < NN){
        int v = g_rowptr[gr][gid] + add;
        g_rowptr[gr][gid] = v;
        g_cursor[gr][gid] = v;
    }
}
__global__ void k_scatter(const int* __restrict__ ei, int gr){
    GDC_LAUNCH();
    int e = blockIdx.x*256 + threadIdx.x;
    int d = 0, s = 0;
    if (e < NE){ d = ei[NE+e]; s = ei[e]; }  // input prefetch (safe pre-wait)
    GDC_WAIT();
    if (e < NE){
        int p = atomicAdd(&g_cursor[gr][d], 1);
        g_col[gr][p] = s;
    }
}

// ---------------- fused update + dual GEMM: 3xTF32, 3 blocks/SM -------------
__global__ void __launch_bounds__(256,3) k_gemm(
        const float* __restrict__ Wl, const float* __restrict__ bl,
        const float* __restrict__ Wr, const float* __restrict__ br,
        const float* __restrict__ gamma, const float* __restrict__ beta,
        int layer, int gr,
        const float* __restrict__ x,
        const float* __restrict__ Wn, const float* __restrict__ bnode)
{
    extern __shared__ float sm[];
    float* ws  = sm + SM_WS;
    float* hsh = sm + SM_HSH;
    float* hsl = sm + SM_HSL;
    float* bc  = sm + SM_BC;
    float* mus = sm + SM_MUS;
    float* rss = sm + SM_RSS;
    __shared__ float wn[320];
    __shared__ float xs[TN*5];

    GDC_LAUNCH();

    int tid  = threadIdx.x;
    int n0t  = blockIdx.x * TN;
    const float* g_hf = g_h[gr];
    const float* g_gf = (const float*)g_g4[gr];

    // ---- safe prologue (inputs only): weights fp32 into smem ----
    for (int i=tid;i<64*128;i+=256){
        int k=i>>7, c=i&127;
        ws[k*WS_STR+c] = (c<64) ? Wl[k*64+c] : Wr[k*64+(c-64)];
    }
    if (tid < 128) bc[tid] = (tid<64) ? bl[tid] : br[tid-64];
    if (layer == 0){
        for (int i=tid;i<320;i+=256) wn[i] = Wn[i];
        for (int i=tid;i<TN*5;i+=256){
            int gi = n0t*5 + i;
            xs[i] = (gi < NN*5) ? x[gi] : 0.f;
        }
    }

    GDC_WAIT();

    if (blockIdx.x == 0 && tid >= 128 && tid < 256){
        int nb = layer & 1, t = tid - 128;
        if (t < 64) g_bnsum[gr][nb][t] = 0.f; else g_bnsq[gr][nb][t-64] = 0.f;
    }

    if (layer == 0){
        __syncthreads();
        for (int i=tid;i<TN*64;i+=256){
            int nl=i>>6, c=i&63; int n=n0t+nl;
            float a = bnode[c];
            #pragma unroll
            for (int k=0;k<5;k++) a = fmaf(xs[nl*5+k], wn[k*64+c], a);
            if (n < NN) g_h[gr][n*64+c] = a; else a = 0.f;
            unsigned hb = f2tf(a);
            float hi = __uint_as_float(hb);
            hsh[nl*HS_STR+c] = hi;
            hsl[nl*HS_STR+c] = __uint_as_float(f2tf(a - hi));
        }
    } else {
        int pb = (layer-1)&1;
        if (tid < 64){
            float mu = g_bnsum[gr][pb][tid]*(1.f/NN);
            float va = g_bnsq[gr][pb][tid]*(1.f/NN) - mu*mu;
            mus[tid] = mu;
            rss[tid] = rsqrtf(va + 1e-5f) * gamma[tid];
        }
        __syncthreads();
        for (int i=tid;i<TN*64;i+=256){
            int nl=i>>6, c=i&63; int n=n0t+nl;
            float hv = 0.f;
            if (n < NN){
                float g  = g_gf[n*64+c];
                float gh = (g - mus[c])*rss[c] + beta[c];
                float el = (gh > 0.f) ? gh : (__expf(gh)-1.f);
                hv = g_hf[n*64+c] + el;
                g_h[gr][n*64+c] = hv;
            }
            unsigned hb = f2tf(hv);
            float hi = __uint_as_float(hb);
            hsh[nl*HS_STR+c] = hi;
            hsl[nl*HS_STR+c] = __uint_as_float(f2tf(hv - hi));
        }
    }
    __syncthreads();

    // ---- tensor-core mainloop: warp tile m32 x n32, 3xTF32 ----
    int lane = tid & 31, wid = tid >> 5;
    int g   = lane >> 2, tig = lane & 3;
    int mgrp = wid & 1;
    int ngrp = wid >> 1;

    float acc[2][4][4];
    #pragma unroll
    for (int nf=0;nf<4;nf++){
        float c0 = bc[ngrp*32 + nf*8 + 2*tig];
        float c1 = bc[ngrp*32 + nf*8 + 2*tig + 1];
        #pragma unroll
        for (int mt=0;mt<2;mt++){
            acc[mt][nf][0]=c0; acc[mt][nf][1]=c1;
            acc[mt][nf][2]=c0; acc[mt][nf][3]=c1;
        }
    }

    #pragma unroll
    for (int kc=0;kc<64;kc+=8){
        unsigned ah[2][4], al[2][4];
        #pragma unroll
        for (int mt=0;mt<2;mt++){
            int m = mgrp*32 + mt*16 + g;
            ah[mt][0] = __float_as_uint(hsh[m*HS_STR     + kc+tig]);
            ah[mt][1] = __float_as_uint(hsh[(m+8)*HS_STR + kc+tig]);
            ah[mt][2] = __float_as_uint(hsh[m*HS_STR     + kc+tig+4]);
            ah[mt][3] = __float_as_uint(hsh[(m+8)*HS_STR + kc+tig+4]);
            al[mt][0] = __float_as_uint(hsl[m*HS_STR     + kc+tig]);
            al[mt][1] = __float_as_uint(hsl[(m+8)*HS_STR + kc+tig]);
            al[mt][2] = __float_as_uint(hsl[m*HS_STR     + kc+tig+4]);
            al[mt][3] = __float_as_uint(hsl[(m+8)*HS_STR + kc+tig+4]);
        }
        #pragma unroll
        for (int nf=0;nf<4;nf++){
            int n = ngrp*32 + nf*8 + g;
            float w0 = ws[(kc+tig)*WS_STR   + n];
            float w1 = ws[(kc+tig+4)*WS_STR + n];
            unsigned bh0 = f2tf(w0);
            unsigned bh1 = f2tf(w1);
            unsigned bl0 = f2tf(w0 - __uint_as_float(bh0));
            unsigned bl1 = f2tf(w1 - __uint_as_float(bh1));
            #pragma unroll
            for (int mt=0;mt<2;mt++){
                MMA_TF32(acc[mt][nf], ah[mt][0],ah[mt][1],ah[mt][2],ah[mt][3], bh0,bh1);
                MMA_TF32(acc[mt][nf], ah[mt][0],ah[mt][1],ah[mt][2],ah[mt][3], bl0,bl1);
                MMA_TF32(acc[mt][nf], al[mt][0],al[mt][1],al[mt][2],al[mt][3], bh0,bh1);
            }
        }
    }

    // ---- epilogue ----
    float2* xl2 = (float2*)g_xl4[gr];
    float2* xr2 = (float2*)g_xr4[gr];
    #pragma unroll
    for (int mt=0;mt<2;mt++){
        int r0 = n0t + mgrp*32 + mt*16 + g;
        #pragma unroll
        for (int nf=0;nf<4;nf++){
            int cg = ngrp*32 + nf*8 + 2*tig;
            float2 v0 = make_float2(acc[mt][nf][0], acc[mt][nf][1]);
            float2 v1 = make_float2(acc[mt][nf][2], acc[mt][nf][3]);
            if (cg < 64){
                if (r0 < NN)   xl2[r0*32 + (cg>>1)]     = v0;
                if (r0+8 < NN) xl2[(r0+8)*32 + (cg>>1)] = v1;
            } else {
                int cc = cg - 64;
                if (r0 < NN)   xr2[r0*32 + (cc>>1)]     = v0;
                if (r0+8 < NN) xr2[(r0+8)*32 + (cc>>1)] = v1;
            }
        }
    }
}

// per-lane 4-feature leaky+dot partial (FMNMX-based leaky)
__device__ __forceinline__ float dot4(float4 xl, float4 xr, float4 a){
    float e0 = xl.x + xr.x; e0 = fmaxf(e0, 0.2f*e0);
    float e1 = xl.y + xr.y; e1 = fmaxf(e1, 0.2f*e1);
    float e2 = xl.z + xr.z; e2 = fmaxf(e2, 0.2f*e2);
    float e3 = xl.w + xr.w; e3 = fmaxf(e3, 0.2f*e3);
    return fmaf(e0,a.x, fmaf(e1,a.y, fmaf(e2,a.z, e3*a.w)));
}

// ---------------- edge aggregation: self-ref softmax, 4-way interleave ------
__global__ void __launch_bounds__(256) k_edge(const float* __restrict__ att,
                                              const float* __restrict__ cb,
                                              int layer, int gr)
{
    __shared__ float bsum[C], bsq[C];

    GDC_LAUNCH();

    int tid = threadIdx.x;
    int n   = blockIdx.x*16 + (tid>>4);
    int l16 = tid & 15;
    unsigned gmask = 0xFu << ((tid&31) & ~3);
    const float4* xl4 = g_xl4[gr];

    if (tid < C){ bsum[tid]=0.f; bsq[tid]=0.f; }
    float4 a  = ((const float4*)att)[l16];
    float4 cb4= ((const float4*)cb)[l16];
    __syncthreads();

    GDC_WAIT();

    float4 xr = g_xr4[gr][n*16 + l16];
    float4 xls = xl4[n*16 + l16];
    float pself;
    {
        float p = dot4(xls, xr, a);
        p += __shfl_xor_sync(gmask, p, 1, 4);
        p += __shfl_xor_sync(gmask, p, 2, 4);
        pself = p;
    }

    float sA = 1.f, sB = 0.f;
    float4 oA = xls;
    float4 oB = make_float4(0.f,0.f,0.f,0.f);
    int beg = g_rowptr[gr][n], end = g_rowptr[gr][n+1];
    const int* col = g_col[gr];
    int j = beg;
    for (; j+3 < end; j += 4){
        int i0 = col[j], i1 = col[j+1], i2 = col[j+2], i3 = col[j+3];
        float4 x0 = xl4[i0*16 + l16];
        float4 x1 = xl4[i1*16 + l16];
        float4 x2 = xl4[i2*16 + l16];
        float4 x3 = xl4[i3*16 + l16];
        float p0 = dot4(x0, xr, a);
        float p1 = dot4(x1, xr, a);
        float p2 = dot4(x2, xr, a);
        float p3 = dot4(x3, xr, a);
        p0 += __shfl_xor_sync(gmask, p0, 1, 4);
        p1 += __shfl_xor_sync(gmask, p1, 1, 4);
        p2 += __shfl_xor_sync(gmask, p2, 1, 4);
        p3 += __shfl_xor_sync(gmask, p3, 1, 4);
        p0 += __shfl_xor_sync(gmask, p0, 2, 4);
        p1 += __shfl_xor_sync(gmask, p1, 2, 4);
        p2 += __shfl_xor_sync(gmask, p2, 2, 4);
        p3 += __shfl_xor_sync(gmask, p3, 2, 4);
        float w0 = __expf(p0 - pself);
        float w1 = __expf(p1 - pself);
        float w2 = __expf(p2 - pself);
        float w3 = __expf(p3 - pself);
        sA += w0; sB += w1; sA += w2; sB += w3;
        oA.x = fmaf(w0, x0.x, oA.x); oB.x = fmaf(w1, x1.x, oB.x);
        oA.y = fmaf(w0, x0.y, oA.y); oB.y = fmaf(w1, x1.y, oB.y);
        oA.z = fmaf(w0, x0.z, oA.z); oB.z = fmaf(w1, x1.z, oB.z);
        oA.w = fmaf(w0, x0.w, oA.w); oB.w = fmaf(w1, x1.w, oB.w);
        oA.x = fmaf(w2, x2.x, oA.x); oB.x = fmaf(w3, x3.x, oB.x);
        oA.y = fmaf(w2, x2.y, oA.y); oB.y = fmaf(w3, x3.y, oB.y);
        oA.z = fmaf(w2, x2.z, oA.z); oB.z = fmaf(w3, x3.z, oB.z);
        oA.w = fmaf(w2, x2.w, oA.w); oB.w = fmaf(w3, x3.w, oB.w);
    }
    for (; j < end; j++){
        int src = col[j];
        float4 xl = xl4[src*16 + l16];
        float p = dot4(xl, xr, a);
        p += __shfl_xor_sync(gmask, p, 1, 4);
        p += __shfl_xor_sync(gmask, p, 2, 4);
        float w = __expf(p - pself);
        sA += w;
        oA.x = fmaf(w, xl.x, oA.x);
        oA.y = fmaf(w, xl.y, oA.y);
        oA.z = fmaf(w, xl.z, oA.z);
        oA.w = fmaf(w, xl.w, oA.w);
    }
    float s = sA + sB;
    float4 o = make_float4(oA.x+oB.x, oA.y+oB.y, oA.z+oB.z, oA.w+oB.w);
    float inv = 1.f/s;
    float4 gv = make_float4(fmaf(o.x,inv,cb4.x), fmaf(o.y,inv,cb4.y),
                            fmaf(o.z,inv,cb4.z), fmaf(o.w,inv,cb4.w));
    g_g4[gr][n*16 + l16] = gv;

    float q0=gv.x, q1=gv.y, q2=gv.z, q3=gv.w;
    float r0=q0*q0, r1=q1*q1, r2=q2*q2, r3=q3*q3;
    q0 += __shfl_xor_sync(0xffffffffu, q0, 16);
    q1 += __shfl_xor_sync(0xffffffffu, q1, 16);
    q2 += __shfl_xor_sync(0xffffffffu, q2, 16);
    q3 += __shfl_xor_sync(0xffffffffu, q3, 16);
    r0 += __shfl_xor_sync(0xffffffffu, r0, 16);
    r1 += __shfl_xor_sync(0xffffffffu, r1, 16);
    r2 += __shfl_xor_sync(0xffffffffu, r2, 16);
    r3 += __shfl_xor_sync(0xffffffffu, r3, 16);
    if ((tid & 31) < 16){
        atomicAdd(&bsum[l16*4+0], q0); atomicAdd(&bsum[l16*4+1], q1);
        atomicAdd(&bsum[l16*4+2], q2); atomicAdd(&bsum[l16*4+3], q3);
        atomicAdd(&bsq [l16*4+0], r0); atomicAdd(&bsq [l16*4+1], r1);
        atomicAdd(&bsq [l16*4+2], r2); atomicAdd(&bsq [l16*4+3], r3);
    }
    __syncthreads();
    if (tid < C){
        int b = layer & 1;
        atomicAdd(&g_bnsum[gr][b][tid], bsum[tid]);
        atomicAdd(&g_bnsq [gr][b][tid], bsq[tid]);
    }
}

// ---------------- pool with fused final update (both graphs, PDL) -----------
__global__ void __launch_bounds__(256) k_pool(const int* __restrict__ b0,
                                              const int* __restrict__ b1,
                                              const float* __restrict__ gamma,
                                              const float* __restrict__ beta)
{
    __shared__ float mus[C], rss[C];
    GDC_LAUNCH();
    GDC_WAIT();
    int gr = blockIdx.x >= 100;
    int blk = blockIdx.x - gr*100;
    const int* batch = gr ? b1 : b0;
    int tid = threadIdx.x;
    if (tid < C){
        float mu = g_bnsum[gr][1][tid]*(1.f/NN);
        float va = g_bnsq[gr][1][tid]*(1.f/NN) - mu*mu;
        mus[tid] = mu;
        rss[tid] = rsqrtf(va + 1e-5f) * gamma[tid];
    }
    __syncthreads();
    const float* g_gf = (const float*)g_g4[gr];
    const float* g_hf = g_h[gr];
    int c = tid & 63, ng = tid >> 6;
    int n0 = blk * 200;
    float acc = 0.f, cnt = 0.f;
    int cur = -1;
    for (int i=ng; i<200; i+=4){
        int n = n0 + i;
        if (n >= NN) break;
        float g  = g_gf[n*64+c];
        float gh = (g - mus[c])*rss[c] + beta[c];
        float el = (gh > 0.f) ? gh : (__expf(gh)-1.f);
        float hv = g_hf[n*64+c] + el;
        int b = batch[n];
        if (b != cur){
            if (cur >= 0){
                atomicAdd(&g_pool[gr*NG*C + cur*C + c], acc);
                if (c == 0) atomicAdd(&g_pcnt[gr*NG + cur], cnt);
            }
            cur = b; acc = 0.f; cnt = 0.f;
        }
        acc += hv; cnt += 1.f;
    }
    if (cur >= 0){
        atomicAdd(&g_pool[gr*NG*C + cur*C + c], acc);
        if (c == 0) atomicAdd(&g_pcnt[gr*NG + cur], cnt);
    }
}

// ---------------- head MLP (normal launch) ----------------------------------
__global__ void __launch_bounds__(256) k_head(
        const float* __restrict__ f1w, const float* __restrict__ f1b,
        const float* __restrict__ f2w, const float* __restrict__ f2b,
        const float* __restrict__ f3w, const float* __restrict__ f3b,
        float* __restrict__ out)
{
    __shared__ float cvec[128], h1[256], h2[128];
    int b = blockIdx.x, tid = threadIdx.x;
    if (tid < 64)
        cvec[tid] = g_pool[b*C+tid] / fmaxf(g_pcnt[b], 1.f);
    else if (tid < 128)
        cvec[tid] = g_pool[NG*C + b*C + (tid-64)] / fmaxf(g_pcnt[NG+b], 1.f);
    __syncthreads();
    float a = f1b[tid];
    for (int k=0;k<128;k++) a = fmaf(cvec[k], f1w[k*256+tid], a);
    h1[tid] = fmaxf(a, 0.f);
    __syncthreads();
    if (tid < 128){
        float a2 = f2b[tid];
        for (int k=0;k<256;k++) a2 = fmaf(h1[k], f2w[k*128+tid], a2);
        h2[tid] = fmaxf(a2, 0.f);
    }
    __syncthreads();
    if (tid == 0){
        float a3 = f3b[0];
        for (int k=0;k<128;k++) a3 = fmaf(h2[k], f3w[k], a3);
        out[b] = a3;
    }
}

// ---------------- launch ----------------------------------------------------
extern "C" void kernel_launch(void* const* d_in, const int* in_sizes, int n_in,
                              void* d_out, int out_size){
    const float *x[2]; const int *ei[2]; const int *bt[2];
    if (in_sizes[1] == 2*NE){
        x[0]=(const float*)d_in[0]; ei[0]=(const int*)d_in[1]; bt[0]=(const int*)d_in[2];
        x[1]=(const float*)d_in[3]; ei[1]=(const int*)d_in[4]; bt[1]=(const int*)d_in[5];
    } else {
        x[0]=(const float*)d_in[0]; x[1]=(const float*)d_in[1];
        ei[0]=(const int*)d_in[2]; ei[1]=(const int*)d_in[3];
        bt[0]=(const int*)d_in[4]; bt[1]=(const int*)d_in[5];
    }
    const float* Wn    =(const float*)d_in[6];
    const float* bnode =(const float*)d_in[7];
    const float* Wl    =(const float*)d_in[8];
    const float* bl    =(const float*)d_in[9];
    const float* Wr    =(const float*)d_in[10];
    const float* br    =(const float*)d_in[11];
    const float* att   =(const float*)d_in[12];
    const float* cbias =(const float*)d_in[13];
    const float* gamma =(const float*)d_in[14];
    const float* beta  =(const float*)d_in[15];
    const float* f1w   =(const float*)d_in[16];
    const float* f1b   =(const float*)d_in[17];
    const float* f2w   =(const float*)d_in[18];
    const float* f2b   =(const float*)d_in[19];
    const float* f3w   =(const float*)d_in[20];
    const float* f3b   =(const float*)d_in[21];

    int gsm = SM_TOT * 4;
    cudaFuncSetAttribute(k_gemm, cudaFuncAttributeMaxDynamicSharedMemorySize, gsm);

    static cudaStream_t s2 = 0;
    static cudaEvent_t  efk = 0, ejn = 0;
    if (!s2){
        cudaStreamCreateWithFlags(&s2, cudaStreamNonBlocking);
        cudaEventCreateWithFlags(&efk, cudaEventDisableTiming);
        cudaEventCreateWithFlags(&ejn, cudaEventDisableTiming);
    }
    cudaStream_t s0 = 0;

    cudaEventRecord(efk, s0);
    cudaStreamWaitEvent(s2, efk, 0);

    cudaLaunchAttribute pdl[1];
    pdl[0].id = cudaLaunchAttributeProgrammaticStreamSerialization;
    pdl[0].val.programmaticStreamSerializationAllowed = 1;

    for (int g=0; g<2; g++){
        cudaStream_t st = g ? s2 : s0;
        k_zero<<<(NN+1023)/1024,1024,0,st>>>(g);
        {
            cudaLaunchConfig_t cfg = {};
            cfg.gridDim = dim3(EBLK,1,1); cfg.blockDim = dim3(256,1,1);
            cfg.stream = st; cfg.attrs = pdl; cfg.numAttrs = 1;
            cudaLaunchKernelEx(&cfg, k_hist, ei[g], g);
        }
        {
            cudaLaunchConfig_t cfg = {};
            cfg.gridDim = dim3(20,1,1); cfg.blockDim = dim3(1024,1,1);
            cfg.stream = st; cfg.attrs = pdl; cfg.numAttrs = 1;
            cudaLaunchKernelEx(&cfg, k_scan1, g);
        }
        {
            cudaLaunchConfig_t cfg = {};
            cfg.gridDim = dim3(20,1,1); cfg.blockDim = dim3(1024,1,1);
            cfg.stream = st; cfg.attrs = pdl; cfg.numAttrs = 1;
            cudaLaunchKernelEx(&cfg, k_scan3, g);
        }
        {
            cudaLaunchConfig_t cfg = {};
            cfg.gridDim = dim3(EBLK,1,1); cfg.blockDim = dim3(256,1,1);
            cfg.stream = st; cfg.attrs = pdl; cfg.numAttrs = 1;
            cudaLaunchKernelEx(&cfg, k_scatter, ei[g], g);
        }
        for (int l=0;l<NL;l++){
            {
                cudaLaunchConfig_t cfg = {};
                cfg.gridDim = dim3(TPG,1,1); cfg.blockDim = dim3(256,1,1);
                cfg.dynamicSmemBytes = gsm; cfg.stream = st;
                cfg.attrs = pdl; cfg.numAttrs = 1;
                cudaLaunchKernelEx(&cfg, k_gemm,
                    Wl+l*C*C, bl+l*C, Wr+l*C*C, br+l*C,
                    gamma+l*C, beta+l*C, l, g, x[g], Wn, bnode);
            }
            {
                cudaLaunchConfig_t cfg = {};
                cfg.gridDim = dim3(EBLK,1,1); cfg.blockDim = dim3(256,1,1);
                cfg.dynamicSmemBytes = 0; cfg.stream = st;
                cfg.attrs = pdl; cfg.numAttrs = 1;
                cudaLaunchKernelEx(&cfg, k_edge,
                    att+l*C, cbias+l*C, l, g);
            }
        }
    }

    cudaEventRecord(ejn, s2);
    cudaStreamWaitEvent(s0, ejn, 0);

    {
        cudaLaunchConfig_t cfg = {};
        cfg.gridDim = dim3(200,1,1); cfg.blockDim = dim3(256,1,1);
        cfg.dynamicSmemBytes = 0; cfg.stream = s0;
        cfg.attrs = pdl; cfg.numAttrs = 1;
        cudaLaunchKernelEx(&cfg, k_pool, bt[0], bt[1], gamma+7*C, beta+7*C);
    }
    k_head<<<NG,256,0,s0>>>(f1w,f1b,f2w,f2b,f3w,f3b,(float*)d_out);
}